// round 2
// baseline (speedup 1.0000x reference)
#include <cuda_runtime.h>
#include <cstdint>

// Problem constants (fixed by the reference)
#define Nn 100000
#define Ee 1600000
#define ND 128
#define ED 32
#define HH 64
#define GG 512

// ---------------- scratch (no allocations allowed) ----------------
__device__ float g_h[Nn * HH];      // node features (current layer)
__device__ float g_t[Nn * HH];      // temp: h @ W
__device__ float g_dinv[Nn];        // deg accumulator -> rsqrt(deg)
__device__ float g_pool[GG * HH];   // per-graph feature sums
__device__ float g_cnt[GG];         // per-graph node counts

// ---------------- small utils ----------------
__global__ void k_zero(float* __restrict__ p, int n) {
    int i = blockIdx.x * blockDim.x + threadIdx.x;
    if (i < n) p[i] = 0.0f;
}

// ---------------- node embed: h = x @ W_node + b_node ----------------
// block = 256 threads, 16 nodes/block. W (128x64 = 32KB) + x rows (8KB) in smem.
__global__ void k_node_embed(const float* __restrict__ x,
                             const float* __restrict__ W,
                             const float* __restrict__ b,
                             float* __restrict__ out) {
    __shared__ float Ws[ND * HH];
    __shared__ float xs[16 * ND];
    int tid = threadIdx.x;
    for (int i = tid; i < ND * HH; i += 256) Ws[i] = W[i];
    int n0 = blockIdx.x * 16;
    for (int i = tid; i < 16 * ND; i += 256) {
        int n = n0 + (i >> 7);
        xs[i] = (n < Nn) ? x[(size_t)n * ND + (i & (ND - 1))] : 0.0f;
    }
    __syncthreads();
    int j = tid & 63;
    int rb = tid >> 6;  // 0..3
    float bj = b[j];
    for (int r = rb; r < 16; r += 4) {
        int n = n0 + r;
        if (n >= Nn) break;
        float acc = bj;
        #pragma unroll
        for (int k = 0; k < ND; k++) acc += xs[r * ND + k] * Ws[k * HH + j];
        out[(size_t)n * HH + j] = acc;
    }
}

// ---------------- edge embed + scatter-to-source ----------------
// warp per edge (grid-stride). lane k holds edge_attr[e][k]; shfl-broadcast MACs.
__global__ void k_edge_embed(const float* __restrict__ ea,
                             const int* __restrict__ src,
                             const float* __restrict__ W,
                             const float* __restrict__ b,
                             float* __restrict__ h) {
    __shared__ float Ws[ED * HH];  // 8KB
    int tid = threadIdx.x;
    for (int i = tid; i < ED * HH; i += blockDim.x) Ws[i] = W[i];
    __syncthreads();
    int lane = tid & 31;
    int warp = blockIdx.x * (blockDim.x >> 5) + (tid >> 5);
    int nwarps = gridDim.x * (blockDim.x >> 5);
    float b0 = b[lane], b1 = b[lane + 32];
    for (int e = warp; e < Ee; e += nwarps) {
        float a = ea[(size_t)e * ED + lane];
        float acc0 = b0, acc1 = b1;
        #pragma unroll
        for (int k = 0; k < 32; k++) {
            float ak = __shfl_sync(0xffffffffu, a, k);
            acc0 += ak * Ws[k * HH + lane];
            acc1 += ak * Ws[k * HH + lane + 32];
        }
        int r = src[e];
        atomicAdd(&h[(size_t)r * HH + lane], acc0);
        atomicAdd(&h[(size_t)r * HH + lane + 32], acc1);
    }
}

// ---------------- degree count over targets ----------------
__global__ void k_deg(const int* __restrict__ col, float* __restrict__ deg) {
    int i = blockIdx.x * blockDim.x + threadIdx.x;
    if (i < Ee) atomicAdd(&deg[col[i]], 1.0f);
}

// deg -> rsqrt(deg + 1)  (self loop guarantees deg >= 1, matches reference)
__global__ void k_dinv(float* __restrict__ d) {
    int i = blockIdx.x * blockDim.x + threadIdx.x;
    if (i < Nn) d[i] = rsqrtf(d[i] + 1.0f);
}

// ---------------- t = (relu?)(h) @ W  (64x64) ----------------
// block = 256 threads, 32 nodes/block; W (16KB) + h rows (8KB) in smem.
template <bool RELU>
__global__ void k_gemm64(const float* __restrict__ h,
                         const float* __restrict__ W,
                         float* __restrict__ out) {
    __shared__ float Ws[HH * HH];
    __shared__ float hs[32 * HH];
    int tid = threadIdx.x;
    for (int i = tid; i < HH * HH; i += 256) Ws[i] = W[i];
    int n0 = blockIdx.x * 32;
    for (int i = tid; i < 32 * HH; i += 256) {
        int n = n0 + (i >> 6);
        float v = (n < Nn) ? h[(size_t)n * HH + (i & 63)] : 0.0f;
        if (RELU) v = fmaxf(v, 0.0f);
        hs[i] = v;
    }
    __syncthreads();
    int j = tid & 63;
    int rb = tid >> 6;
    for (int r = rb; r < 32; r += 4) {
        int n = n0 + r;
        if (n >= Nn) continue;
        float acc = 0.0f;
        #pragma unroll
        for (int k = 0; k < HH; k++) acc += hs[r * HH + k] * Ws[k * HH + j];
        out[(size_t)n * HH + j] = acc;
    }
}

// ---------------- h = b + t * dinv^2 (self-loop + bias init) ----------------
__global__ void k_selfinit(const float* __restrict__ t,
                           const float* __restrict__ dinv,
                           const float* __restrict__ b,
                           float* __restrict__ h) {
    int i = blockIdx.x * blockDim.x + threadIdx.x;
    if (i < Nn * HH) {
        int n = i >> 6;
        float di = dinv[n];
        h[i] = b[i & 63] + t[i] * di * di;
    }
}

// ---------------- conv scatter: h[col] += t[row] * dinv[row]*dinv[col] ----------------
__global__ void k_conv_scatter(const float* __restrict__ t,
                               const int* __restrict__ row,
                               const int* __restrict__ col,
                               const float* __restrict__ dinv,
                               float* __restrict__ h) {
    int tid = threadIdx.x;
    int lane = tid & 31;
    int warp = blockIdx.x * (blockDim.x >> 5) + (tid >> 5);
    int nwarps = gridDim.x * (blockDim.x >> 5);
    for (int e = warp; e < Ee; e += nwarps) {
        int r = row[e];
        int c = col[e];
        float nrm = dinv[r] * dinv[c];
        float v0 = t[(size_t)r * HH + lane] * nrm;
        float v1 = t[(size_t)r * HH + lane + 32] * nrm;
        atomicAdd(&h[(size_t)c * HH + lane], v0);
        atomicAdd(&h[(size_t)c * HH + lane + 32], v1);
    }
}

// ---------------- global mean pool (sum + count) ----------------
__global__ void k_pool(const float* __restrict__ h,
                       const int* __restrict__ batch,
                       float* __restrict__ pool,
                       float* __restrict__ cnt) {
    int tid = threadIdx.x;
    int lane = tid & 31;
    int warp = blockIdx.x * (blockDim.x >> 5) + (tid >> 5);
    int nwarps = gridDim.x * (blockDim.x >> 5);
    for (int n = warp; n < Nn; n += nwarps) {
        int g = batch[n];
        atomicAdd(&pool[(size_t)g * HH + lane], h[(size_t)n * HH + lane]);
        atomicAdd(&pool[(size_t)g * HH + lane + 32], h[(size_t)n * HH + lane + 32]);
        if (lane == 0) atomicAdd(&cnt[g], 1.0f);
    }
}

// ---------------- classifier head: out[g] = relu(mean @ Wc1 + bc1) @ Wc2 + bc2 ----------------
__global__ void k_head(const float* __restrict__ pool,
                       const float* __restrict__ cnt,
                       const float* __restrict__ Wc1,
                       const float* __restrict__ bc1,
                       const float* __restrict__ Wc2,
                       const float* __restrict__ bc2,
                       float* __restrict__ out) {
    int g = blockIdx.x;
    int j = threadIdx.x;  // 32 threads
    float inv = 1.0f / fmaxf(cnt[g], 1.0f);
    float acc = bc1[j];
    #pragma unroll
    for (int k = 0; k < HH; k++) acc += pool[(size_t)g * HH + k] * inv * Wc1[k * 32 + j];
    acc = fmaxf(acc, 0.0f);
    float v = acc * Wc2[j];
    #pragma unroll
    for (int o = 16; o > 0; o >>= 1) v += __shfl_down_sync(0xffffffffu, v, o);
    if (j == 0) out[g] = v + bc2[0];
}

// ---------------- launch ----------------
extern "C" void kernel_launch(void* const* d_in, const int* in_sizes, int n_in,
                              void* d_out, int out_size) {
    const float* x      = (const float*)d_in[0];
    const int*   ei     = (const int*)d_in[1];   // [2,E] int32: ei = row(src), ei+E = col(dst)
    const float* eattr  = (const float*)d_in[2];
    const int*   batch  = (const int*)d_in[3];
    const float* W_node = (const float*)d_in[4];
    const float* b_node = (const float*)d_in[5];
    const float* W_edge = (const float*)d_in[6];
    const float* b_edge = (const float*)d_in[7];
    const float* W_g1   = (const float*)d_in[8];
    const float* b_g1   = (const float*)d_in[9];
    const float* W_g2   = (const float*)d_in[10];
    const float* b_g2   = (const float*)d_in[11];
    const float* W_g3   = (const float*)d_in[12];
    const float* b_g3   = (const float*)d_in[13];
    const float* W_c1   = (const float*)d_in[14];
    const float* b_c1   = (const float*)d_in[15];
    const float* W_c2   = (const float*)d_in[16];
    const float* b_c2   = (const float*)d_in[17];
    float* out = (float*)d_out;

    const int* row = ei;        // source
    const int* col = ei + Ee;   // target

    float *h, *t, *dinv, *pool, *cnt;
    cudaGetSymbolAddress((void**)&h,    g_h);
    cudaGetSymbolAddress((void**)&t,    g_t);
    cudaGetSymbolAddress((void**)&dinv, g_dinv);
    cudaGetSymbolAddress((void**)&pool, g_pool);
    cudaGetSymbolAddress((void**)&cnt,  g_cnt);

    const int EDGE_BLOCKS = 148 * 16;   // persistent warp-per-edge grids

    // degree / dinv (independent of h pipeline, launched first)
    k_zero<<<(Nn + 255) / 256, 256>>>(dinv, Nn);
    k_deg<<<(Ee + 255) / 256, 256>>>(col, dinv);
    k_dinv<<<(Nn + 255) / 256, 256>>>(dinv);

    // node embed + edge embed scatter
    k_node_embed<<<(Nn + 15) / 16, 256>>>(x, W_node, b_node, h);
    k_edge_embed<<<EDGE_BLOCKS, 256>>>(eattr, row, W_edge, b_edge, h);

    // GCN layer 1 (no relu on input)
    k_gemm64<false><<<(Nn + 31) / 32, 256>>>(h, W_g1, t);
    k_selfinit<<<(Nn * HH + 255) / 256, 256>>>(t, dinv, b_g1, h);
    k_conv_scatter<<<EDGE_BLOCKS, 256>>>(t, row, col, dinv, h);

    // GCN layer 2 (relu fused into gemm input)
    k_gemm64<true><<<(Nn + 31) / 32, 256>>>(h, W_g2, t);
    k_selfinit<<<(Nn * HH + 255) / 256, 256>>>(t, dinv, b_g2, h);
    k_conv_scatter<<<EDGE_BLOCKS, 256>>>(t, row, col, dinv, h);

    // GCN layer 3 (relu fused into gemm input; output not relu'd)
    k_gemm64<true><<<(Nn + 31) / 32, 256>>>(h, W_g3, t);
    k_selfinit<<<(Nn * HH + 255) / 256, 256>>>(t, dinv, b_g3, h);
    k_conv_scatter<<<EDGE_BLOCKS, 256>>>(t, row, col, dinv, h);

    // mean pool + head
    k_zero<<<(GG * HH + 255) / 256, 256>>>(pool, GG * HH);
    k_zero<<<(GG + 255) / 256, 256>>>(cnt, GG);
    k_pool<<<148 * 8, 256>>>(h, batch, pool, cnt);
    k_head<<<GG, 32>>>(pool, cnt, W_c1, b_c1, W_c2, b_c2, out);
}

// round 4
// speedup vs baseline: 1.4543x; 1.4543x over previous
#include <cuda_runtime.h>
#include <cstdint>

#define Nn 100000
#define Ee 1600000
#define ND 128
#define ED 32
#define HH 64
#define GG 512

// ---------------- scratch ----------------
__device__ float g_h[Nn * HH];
__device__ float g_t[Nn * HH];
__device__ float g_dinv[Nn];
__device__ float g_pool[GG * HH];
__device__ float g_cnt[GG];

// vector reduction (sm_90+)
__device__ __forceinline__ void red4(float* p, float4 v) {
    asm volatile("red.global.add.v4.f32 [%0], {%1,%2,%3,%4};"
                 :: "l"(p), "f"(v.x), "f"(v.y), "f"(v.z), "f"(v.w) : "memory");
}

__global__ void k_zero(float* __restrict__ p, int n) {
    int i = blockIdx.x * blockDim.x + threadIdx.x;
    if (i < n) p[i] = 0.0f;
}

__global__ void k_deg(const int* __restrict__ col, float* __restrict__ deg) {
    int i = blockIdx.x * blockDim.x + threadIdx.x;
    if (i < Ee) atomicAdd(&deg[col[i]], 1.0f);
}

__global__ void k_dinv(float* __restrict__ d) {
    int i = blockIdx.x * blockDim.x + threadIdx.x;
    if (i < Nn) d[i] = rsqrtf(d[i] + 1.0f);
}

// ---------------- node embed: out = x @ W + b ----------------
// 32 rows/block, 128 threads, 4 rows x 4 cols per thread.
// Static smem: W 32KB + x-tile 16KB = 48KB exactly (no dynamic smem needed).
__global__ void __launch_bounds__(128) k_node_embed(
        const float* __restrict__ x,
        const float* __restrict__ W,
        const float* __restrict__ b,
        float* __restrict__ out) {
    __shared__ float Ws[ND * HH];      // 32KB
    __shared__ float xs[32 * ND];      // 16KB (no padding: reads are warp-broadcast)
    int tid = threadIdx.x;
    for (int i = tid; i < ND * HH / 4; i += 128)
        ((float4*)Ws)[i] = ((const float4*)W)[i];
    int n0 = blockIdx.x * 32;
    for (int i = tid; i < 32 * (ND / 4); i += 128) {
        int r = i >> 5;       // 32 float4 per row
        int c4 = i & 31;
        int n = n0 + r;
        float4 v = (n < Nn) ? ((const float4*)x)[(size_t)n * (ND / 4) + c4]
                            : make_float4(0.f, 0.f, 0.f, 0.f);
        *(float4*)&xs[r * ND + c4 * 4] = v;
    }
    __syncthreads();
    int ch = tid & 15;        // col chunk (features 4ch..4ch+3)
    int rg = tid >> 4;        // row group 0..7 (rows 4rg..4rg+3)
    float4 bj = ((const float4*)b)[ch];
    float4 a0 = bj, a1 = bj, a2 = bj, a3 = bj;
    #pragma unroll 4
    for (int k = 0; k < ND; k++) {
        float4 w = *(const float4*)&Ws[k * HH + ch * 4];
        float h0 = xs[(rg * 4 + 0) * ND + k];
        float h1 = xs[(rg * 4 + 1) * ND + k];
        float h2 = xs[(rg * 4 + 2) * ND + k];
        float h3 = xs[(rg * 4 + 3) * ND + k];
        a0.x += h0 * w.x; a0.y += h0 * w.y; a0.z += h0 * w.z; a0.w += h0 * w.w;
        a1.x += h1 * w.x; a1.y += h1 * w.y; a1.z += h1 * w.z; a1.w += h1 * w.w;
        a2.x += h2 * w.x; a2.y += h2 * w.y; a2.z += h2 * w.z; a2.w += h2 * w.w;
        a3.x += h3 * w.x; a3.y += h3 * w.y; a3.z += h3 * w.z; a3.w += h3 * w.w;
    }
    float4 accs[4] = {a0, a1, a2, a3};
    #pragma unroll
    for (int r = 0; r < 4; r++) {
        int n = n0 + rg * 4 + r;
        if (n < Nn) ((float4*)out)[(size_t)n * (HH / 4) + ch] = accs[r];
    }
}

// ---------------- GCN gemm fused with self-loop init ----------------
// t = relu?(h) @ W ; hout = b + t*dinv^2. 64 rows/block, 256 thr, 4x4/thread.
template <bool RELU>
__global__ void __launch_bounds__(256) k_gcn_gemm(
        const float* hin,
        const float* __restrict__ W,
        const float* __restrict__ b,
        const float* __restrict__ dinv,
        float* __restrict__ t,
        float* hout) {
    __shared__ float Ws[HH * HH];          // 16KB
    __shared__ float hs[64 * HH];          // 16KB (warp-broadcast reads)
    int tid = threadIdx.x;
    for (int i = tid; i < HH * HH / 4; i += 256)
        ((float4*)Ws)[i] = ((const float4*)W)[i];
    int n0 = blockIdx.x * 64;
    for (int i = tid; i < 64 * (HH / 4); i += 256) {
        int r = i >> 4;
        int c4 = i & 15;
        int n = n0 + r;
        float4 v = (n < Nn) ? ((const float4*)hin)[(size_t)n * (HH / 4) + c4]
                            : make_float4(0.f, 0.f, 0.f, 0.f);
        if (RELU) {
            v.x = fmaxf(v.x, 0.f); v.y = fmaxf(v.y, 0.f);
            v.z = fmaxf(v.z, 0.f); v.w = fmaxf(v.w, 0.f);
        }
        *(float4*)&hs[r * HH + c4 * 4] = v;
    }
    __syncthreads();
    int ch = tid & 15;
    int rg = tid >> 4;
    float4 a0 = {0,0,0,0}, a1 = {0,0,0,0}, a2 = {0,0,0,0}, a3 = {0,0,0,0};
    #pragma unroll 4
    for (int k = 0; k < HH; k++) {
        float4 w = *(const float4*)&Ws[k * HH + ch * 4];
        float h0 = hs[(rg * 4 + 0) * HH + k];
        float h1 = hs[(rg * 4 + 1) * HH + k];
        float h2 = hs[(rg * 4 + 2) * HH + k];
        float h3 = hs[(rg * 4 + 3) * HH + k];
        a0.x += h0 * w.x; a0.y += h0 * w.y; a0.z += h0 * w.z; a0.w += h0 * w.w;
        a1.x += h1 * w.x; a1.y += h1 * w.y; a1.z += h1 * w.z; a1.w += h1 * w.w;
        a2.x += h2 * w.x; a2.y += h2 * w.y; a2.z += h2 * w.z; a2.w += h2 * w.w;
        a3.x += h3 * w.x; a3.y += h3 * w.y; a3.z += h3 * w.z; a3.w += h3 * w.w;
    }
    float4 accs[4] = {a0, a1, a2, a3};
    float4 bj = ((const float4*)b)[ch];
    #pragma unroll
    for (int r = 0; r < 4; r++) {
        int n = n0 + rg * 4 + r;
        if (n < Nn) {
            float4 acc = accs[r];
            ((float4*)t)[(size_t)n * (HH / 4) + ch] = acc;
            float di = dinv[n];
            float s = di * di;
            float4 hv;
            hv.x = bj.x + acc.x * s; hv.y = bj.y + acc.y * s;
            hv.z = bj.z + acc.z * s; hv.w = bj.w + acc.w * s;
            ((float4*)hout)[(size_t)n * (HH / 4) + ch] = hv;
        }
    }
}

// ---------------- edge embed + scatter-to-source ----------------
// half-warp per edge; lane computes float4 feature chunk; vector RED output.
__global__ void k_edge_embed(const float* __restrict__ ea,
                             const int* __restrict__ src,
                             const float* __restrict__ W,
                             const float* __restrict__ b,
                             float* __restrict__ h) {
    __shared__ float Ws[ED * HH];  // 8KB
    int tid = threadIdx.x;
    for (int i = tid; i < ED * HH / 4; i += blockDim.x)
        ((float4*)Ws)[i] = ((const float4*)W)[i];
    __syncthreads();
    int lane = tid & 31;
    int hl = lane & 15;
    int half = lane >> 4;
    int warp = blockIdx.x * (blockDim.x >> 5) + (tid >> 5);
    int nw = gridDim.x * (blockDim.x >> 5);
    float4 bj = ((const float4*)b)[hl];
    for (int e2 = warp; e2 < Ee / 2; e2 += nw) {
        int e = e2 * 2 + half;
        float at0 = ea[(size_t)e * ED + hl];
        float at1 = ea[(size_t)e * ED + 16 + hl];
        float4 acc = bj;
        #pragma unroll
        for (int k = 0; k < 16; k++) {
            float ak = __shfl_sync(0xffffffffu, at0, (half << 4) + k);
            float4 w = *(const float4*)&Ws[k * HH + hl * 4];
            acc.x += ak * w.x; acc.y += ak * w.y; acc.z += ak * w.z; acc.w += ak * w.w;
        }
        #pragma unroll
        for (int k = 0; k < 16; k++) {
            float ak = __shfl_sync(0xffffffffu, at1, (half << 4) + k);
            float4 w = *(const float4*)&Ws[(16 + k) * HH + hl * 4];
            acc.x += ak * w.x; acc.y += ak * w.y; acc.z += ak * w.z; acc.w += ak * w.w;
        }
        int r = src[e];
        red4(&h[(size_t)r * HH + hl * 4], acc);
    }
}

// ---------------- conv scatter: h[c] += t[r] * dinv[r]*dinv[c] ----------------
// 16 threads per edge, one float4 chunk each, vector RED.
__global__ void k_conv_scatter(const float4* __restrict__ t4,
                               const int* __restrict__ row,
                               const int* __restrict__ col,
                               const float* __restrict__ dinv,
                               float* __restrict__ h) {
    int tid = blockIdx.x * blockDim.x + threadIdx.x;
    int hl = tid & 15;
    int ei = tid >> 4;
    int stride = (gridDim.x * blockDim.x) >> 4;
    for (int e = ei; e < Ee; e += stride) {
        int r = row[e];
        int c = col[e];
        float nrm = dinv[r] * dinv[c];
        float4 v = t4[(size_t)r * (HH / 4) + hl];
        v.x *= nrm; v.y *= nrm; v.z *= nrm; v.w *= nrm;
        red4(&h[(size_t)c * HH + hl * 4], v);
    }
}

// ---------------- global mean pool ----------------
__global__ void k_pool(const float* __restrict__ h,
                       const int* __restrict__ batch,
                       float* __restrict__ pool,
                       float* __restrict__ cnt) {
    int tid = blockIdx.x * blockDim.x + threadIdx.x;
    int hl = tid & 15;
    int ni = tid >> 4;
    int stride = (gridDim.x * blockDim.x) >> 4;
    for (int n = ni; n < Nn; n += stride) {
        int g = batch[n];
        float4 v = ((const float4*)h)[(size_t)n * (HH / 4) + hl];
        red4(&pool[(size_t)g * HH + hl * 4], v);
        if (hl == 0) atomicAdd(&cnt[g], 1.0f);
    }
}

// ---------------- classifier head ----------------
__global__ void k_head(const float* __restrict__ pool,
                       const float* __restrict__ cnt,
                       const float* __restrict__ Wc1,
                       const float* __restrict__ bc1,
                       const float* __restrict__ Wc2,
                       const float* __restrict__ bc2,
                       float* __restrict__ out) {
    int g = blockIdx.x;
    int j = threadIdx.x;  // 32 threads
    float inv = 1.0f / fmaxf(cnt[g], 1.0f);
    float acc = bc1[j];
    #pragma unroll
    for (int k = 0; k < HH; k++) acc += pool[(size_t)g * HH + k] * inv * Wc1[k * 32 + j];
    acc = fmaxf(acc, 0.0f);
    float v = acc * Wc2[j];
    #pragma unroll
    for (int o = 16; o > 0; o >>= 1) v += __shfl_down_sync(0xffffffffu, v, o);
    if (j == 0) out[g] = v + bc2[0];
}

// ---------------- launch ----------------
extern "C" void kernel_launch(void* const* d_in, const int* in_sizes, int n_in,
                              void* d_out, int out_size) {
    const float* x      = (const float*)d_in[0];
    const int*   ei     = (const int*)d_in[1];
    const float* eattr  = (const float*)d_in[2];
    const int*   batch  = (const int*)d_in[3];
    const float* W_node = (const float*)d_in[4];
    const float* b_node = (const float*)d_in[5];
    const float* W_edge = (const float*)d_in[6];
    const float* b_edge = (const float*)d_in[7];
    const float* W_g1   = (const float*)d_in[8];
    const float* b_g1   = (const float*)d_in[9];
    const float* W_g2   = (const float*)d_in[10];
    const float* b_g2   = (const float*)d_in[11];
    const float* W_g3   = (const float*)d_in[12];
    const float* b_g3   = (const float*)d_in[13];
    const float* W_c1   = (const float*)d_in[14];
    const float* b_c1   = (const float*)d_in[15];
    const float* W_c2   = (const float*)d_in[16];
    const float* b_c2   = (const float*)d_in[17];
    float* out = (float*)d_out;

    const int* row = ei;        // source
    const int* col = ei + Ee;   // target

    float *h, *t, *dinv, *pool, *cnt;
    cudaGetSymbolAddress((void**)&h,    g_h);
    cudaGetSymbolAddress((void**)&t,    g_t);
    cudaGetSymbolAddress((void**)&dinv, g_dinv);
    cudaGetSymbolAddress((void**)&pool, g_pool);
    cudaGetSymbolAddress((void**)&cnt,  g_cnt);

    const int EDGE_BLOCKS = 148 * 16;

    // degree / dinv
    k_zero<<<(Nn + 255) / 256, 256>>>(dinv, Nn);
    k_deg<<<(Ee + 255) / 256, 256>>>(col, dinv);
    k_dinv<<<(Nn + 255) / 256, 256>>>(dinv);

    // embeddings
    k_node_embed<<<(Nn + 31) / 32, 128>>>(x, W_node, b_node, h);
    k_edge_embed<<<EDGE_BLOCKS, 256>>>(eattr, row, W_edge, b_edge, h);

    // GCN layers (gemm fused with self-loop+bias init, then edge scatter)
    k_gcn_gemm<false><<<(Nn + 63) / 64, 256>>>(h, W_g1, b_g1, dinv, t, h);
    k_conv_scatter<<<EDGE_BLOCKS, 256>>>((const float4*)t, row, col, dinv, h);

    k_gcn_gemm<true><<<(Nn + 63) / 64, 256>>>(h, W_g2, b_g2, dinv, t, h);
    k_conv_scatter<<<EDGE_BLOCKS, 256>>>((const float4*)t, row, col, dinv, h);

    k_gcn_gemm<true><<<(Nn + 63) / 64, 256>>>(h, W_g3, b_g3, dinv, t, h);
    k_conv_scatter<<<EDGE_BLOCKS, 256>>>((const float4*)t, row, col, dinv, h);

    // pool + head
    k_zero<<<(GG * HH + 255) / 256, 256>>>(pool, GG * HH);
    k_zero<<<(GG + 255) / 256, 256>>>(cnt, GG);
    k_pool<<<148 * 8, 256>>>(h, batch, pool, cnt);
    k_head<<<GG, 32>>>(pool, cnt, W_c1, b_c1, W_c2, b_c2, out);
}